// round 1
// baseline (speedup 1.0000x reference)
#include <cuda_runtime.h>
#include <math.h>

// FixedRadiusNeighborQuery: for each query point, find up to LIMIT nearest
// points (within RADIUS, same ragged batch segment), sorted by squared
// distance ascending (ties: lower index first).
//
// Inputs (metadata order):
//   d_in[0] points            float32 (N*3)
//   d_in[1] row_splits        int32   (B+1)
//   d_in[2] output_points     float32 (Q*3)
//   d_in[3] output_row_splits int32   (B+1)
// Output: float32, [ idx_as_float (Q*LIMIT) | dist (Q*LIMIT) ]
//
// Numerics deliberately mirror the JAX reference:
//   p2 = (x*x + y*y) + z*z              (rounded squares, left-assoc adds)
//   dot = fma(z,pz, fma(y,py, x*px))    (ascending-k fma chain, as sgemm K=3)
//   d2  = (q2 + p2) - 2*dot             (2*dot exact; that association)
//   d2  = max(d2, 0);  valid = d2 <= 0.09f
//   dist = sqrtf(max(d2, 1e-12f))

#define FRNQ_LIMIT 32
#define FRNQ_TILE  2048
#define FRNQ_WARPS_PER_BLOCK 16
#define FRNQ_THREADS (FRNQ_WARPS_PER_BLOCK * 32)

__global__ __launch_bounds__(FRNQ_THREADS)
void frnq_kernel(const float* __restrict__ points,
                 const int*   __restrict__ row_splits,   int n_rs,
                 const float* __restrict__ qpts,
                 const int*   __restrict__ q_splits,     int n_qs,
                 int Q,
                 float* __restrict__ out_idx,
                 float* __restrict__ out_dist)
{
    __shared__ float4 tile[FRNQ_TILE];

    const int tid  = threadIdx.x;
    const int lane = tid & 31;
    const int warp = tid >> 5;
    const int q    = blockIdx.x * FRNQ_WARPS_PER_BLOCK + warp;
    const bool active_q = (q < Q);

    const float R2  = 0.09f;                        // float(RADIUS*RADIUS)
    const float INF = __int_as_float(0x7f800000);

    // --- batch id of this warp's query (searchsorted right - 1) ---
    int qb = 0;
    {
        int qq = active_q ? q : (Q - 1);
        for (int i = 1; i < n_qs; ++i)
            if (q_splits[i] <= qq) qb = i;
    }
    // --- batch range covered by this block's queries ---
    int qfirst = blockIdx.x * FRNQ_WARPS_PER_BLOCK;
    int qlast  = qfirst + FRNQ_WARPS_PER_BLOCK - 1;
    if (qlast >= Q) qlast = Q - 1;
    int b0 = 0, b1 = 0;
    for (int i = 1; i < n_qs; ++i) {
        if (q_splits[i] <= qfirst) b0 = i;
        if (q_splits[i] <= qlast)  b1 = i;
    }

    // --- query coordinates ---
    float qx = 0.f, qy = 0.f, qz = 0.f, q2 = 0.f;
    if (active_q) {
        qx = qpts[3 * q + 0];
        qy = qpts[3 * q + 1];
        qz = qpts[3 * q + 2];
        q2 = __fadd_rn(__fadd_rn(__fmul_rn(qx, qx), __fmul_rn(qy, qy)),
                       __fmul_rn(qz, qz));
    }

    // --- per-lane sorted candidate list (d2 asc; ties keep earlier idx) ---
    float ld[FRNQ_LIMIT];
    int   li[FRNQ_LIMIT];
    int   n = 0;

    for (int b = b0; b <= b1; ++b) {
        const int ps = row_splits[b];
        const int pe = row_splits[b + 1];
        const bool my_batch = active_q && (qb == b);

        for (int t = ps; t < pe; t += FRNQ_TILE) {
            int cnt = pe - t;
            if (cnt > FRNQ_TILE) cnt = FRNQ_TILE;

            __syncthreads();
            for (int i = tid; i < cnt; i += FRNQ_THREADS) {
                float x = points[3 * (t + i) + 0];
                float y = points[3 * (t + i) + 1];
                float z = points[3 * (t + i) + 2];
                float pp = __fadd_rn(__fadd_rn(__fmul_rn(x, x), __fmul_rn(y, y)),
                                     __fmul_rn(z, z));
                tile[i] = make_float4(x, y, z, pp);
            }
            __syncthreads();

            if (my_batch) {
                for (int k = lane; k < cnt; k += 32) {
                    float4 p = tile[k];
                    float dot = __fmaf_rn(qz, p.z,
                                __fmaf_rn(qy, p.y, __fmul_rn(qx, p.x)));
                    float d2  = __fadd_rn(__fadd_rn(q2, p.w),
                                          -__fmul_rn(2.0f, dot));
                    d2 = fmaxf(d2, 0.0f);
                    if (d2 <= R2) {
                        if (n < FRNQ_LIMIT || d2 < ld[FRNQ_LIMIT - 1]) {
                            int j = (n < FRNQ_LIMIT) ? n : (FRNQ_LIMIT - 1);
                            while (j > 0 && ld[j - 1] > d2) {
                                ld[j] = ld[j - 1];
                                li[j] = li[j - 1];
                                --j;
                            }
                            ld[j] = d2;
                            li[j] = t + k;
                            if (n < FRNQ_LIMIT) ++n;
                        }
                    }
                }
            }
        }
    }

    if (!active_q) return;

    // --- warp merge of 32 sorted lane lists: 32 rounds of argmin(d2, idx) ---
    int   pos = 0;
    float hd  = (n > 0) ? ld[0] : INF;
    int   hi  = (n > 0) ? li[0] : 0x7fffffff;
    float rd  = INF;
    int   ri  = -1;

    #pragma unroll
    for (int r = 0; r < FRNQ_LIMIT; ++r) {
        float bd = hd;
        int   bi = hi;
        int   bl = lane;
        #pragma unroll
        for (int off = 16; off > 0; off >>= 1) {
            float od = __shfl_xor_sync(0xffffffffu, bd, off);
            int   oi = __shfl_xor_sync(0xffffffffu, bi, off);
            int   ol = __shfl_xor_sync(0xffffffffu, bl, off);
            if (od < bd || (od == bd && oi < bi)) { bd = od; bi = oi; bl = ol; }
        }
        if (lane == bl) {
            ++pos;
            if (pos < n) { hd = ld[pos]; hi = li[pos]; }
            else         { hd = INF;     hi = 0x7fffffff; }
        }
        if (r == lane) { rd = bd; ri = bi; }
    }

    const size_t o   = (size_t)q * FRNQ_LIMIT + lane;
    const bool   val = (rd < 1e29f);
    out_idx[o]  = val ? (float)ri : -1.0f;
    out_dist[o] = val ? sqrtf(fmaxf(rd, 1e-12f)) : 0.0f;
}

extern "C" void kernel_launch(void* const* d_in, const int* in_sizes, int n_in,
                              void* d_out, int out_size)
{
    const float* points     = (const float*)d_in[0];
    const int*   row_splits = (const int*)  d_in[1];
    const float* qpts       = (const float*)d_in[2];
    const int*   q_splits   = (const int*)  d_in[3];

    const int n_rs = in_sizes[1];
    const int n_qs = in_sizes[3];
    const int Q    = in_sizes[2] / 3;

    float* out_idx  = (float*)d_out;
    float* out_dist = out_idx + (size_t)Q * FRNQ_LIMIT;

    const int blocks = (Q + FRNQ_WARPS_PER_BLOCK - 1) / FRNQ_WARPS_PER_BLOCK;
    frnq_kernel<<<blocks, FRNQ_THREADS>>>(points, row_splits, n_rs,
                                          qpts, q_splits, n_qs,
                                          Q, out_idx, out_dist);
}

// round 2
// speedup vs baseline: 1.0433x; 1.0433x over previous
#include <cuda_runtime.h>
#include <math.h>

// FixedRadiusNeighborQuery: for each query point, find up to LIMIT nearest
// points (within RADIUS, same ragged batch segment), sorted by squared
// distance ascending (ties: lower index first).
//
// Inputs (metadata order):
//   d_in[0] points            float32 (N*3)
//   d_in[1] row_splits        int32   (B+1)
//   d_in[2] output_points     float32 (Q*3)
//   d_in[3] output_row_splits int32   (B+1)
// Output: float32, [ idx_as_float (Q*LIMIT) | dist (Q*LIMIT) ]
//
// Numerics deliberately mirror the JAX reference:
//   p2 = (x*x + y*y) + z*z              (rounded squares, left-assoc adds)
//   dot = fma(z,pz, fma(y,py, x*px))    (ascending-k fma chain, as sgemm K=3)
//   d2  = (q2 + p2) - 2*dot             (2*dot exact; that association)
//   d2  = max(d2, 0);  valid = d2 <= 0.09f
//   dist = sqrtf(max(d2, 1e-12f))

#define FRNQ_LIMIT 32
#define FRNQ_TILE  2048
#define FRNQ_WARPS_PER_BLOCK 16
#define FRNQ_THREADS (FRNQ_WARPS_PER_BLOCK * 32)

__global__ __launch_bounds__(FRNQ_THREADS)
void frnq_kernel(const float* __restrict__ points,
                 const int*   __restrict__ row_splits,   int n_rs,
                 const float* __restrict__ qpts,
                 const int*   __restrict__ q_splits,     int n_qs,
                 int Q,
                 float* __restrict__ out_idx,
                 float* __restrict__ out_dist)
{
    __shared__ float4 tile[FRNQ_TILE];

    const int tid  = threadIdx.x;
    const int lane = tid & 31;
    const int warp = tid >> 5;
    const int q    = blockIdx.x * FRNQ_WARPS_PER_BLOCK + warp;
    const bool active_q = (q < Q);

    const float R2  = 0.09f;                        // float(RADIUS*RADIUS)
    const float INF = __int_as_float(0x7f800000);

    // --- batch id of this warp's query (searchsorted right - 1) ---
    int qb = 0;
    {
        int qq = active_q ? q : (Q - 1);
        for (int i = 1; i < n_qs; ++i)
            if (q_splits[i] <= qq) qb = i;
    }
    // --- batch range covered by this block's queries ---
    int qfirst = blockIdx.x * FRNQ_WARPS_PER_BLOCK;
    int qlast  = qfirst + FRNQ_WARPS_PER_BLOCK - 1;
    if (qlast >= Q) qlast = Q - 1;
    int b0 = 0, b1 = 0;
    for (int i = 1; i < n_qs; ++i) {
        if (q_splits[i] <= qfirst) b0 = i;
        if (q_splits[i] <= qlast)  b1 = i;
    }

    // --- query coordinates ---
    float qx = 0.f, qy = 0.f, qz = 0.f, q2 = 0.f;
    if (active_q) {
        qx = qpts[3 * q + 0];
        qy = qpts[3 * q + 1];
        qz = qpts[3 * q + 2];
        q2 = __fadd_rn(__fadd_rn(__fmul_rn(qx, qx), __fmul_rn(qy, qy)),
                       __fmul_rn(qz, qz));
    }

    // --- per-lane sorted candidate list (d2 asc; ties keep earlier idx) ---
    float ld[FRNQ_LIMIT];
    int   li[FRNQ_LIMIT];
    int   n = 0;

    for (int b = b0; b <= b1; ++b) {
        const int ps = row_splits[b];
        const int pe = row_splits[b + 1];
        const bool my_batch = active_q && (qb == b);

        for (int t = ps; t < pe; t += FRNQ_TILE) {
            int cnt = pe - t;
            if (cnt > FRNQ_TILE) cnt = FRNQ_TILE;

            __syncthreads();
            for (int i = tid; i < cnt; i += FRNQ_THREADS) {
                float x = points[3 * (t + i) + 0];
                float y = points[3 * (t + i) + 1];
                float z = points[3 * (t + i) + 2];
                float pp = __fadd_rn(__fadd_rn(__fmul_rn(x, x), __fmul_rn(y, y)),
                                     __fmul_rn(z, z));
                tile[i] = make_float4(x, y, z, pp);
            }
            __syncthreads();

            if (my_batch) {
                for (int k = lane; k < cnt; k += 32) {
                    float4 p = tile[k];
                    float dot = __fmaf_rn(qz, p.z,
                                __fmaf_rn(qy, p.y, __fmul_rn(qx, p.x)));
                    float d2  = __fadd_rn(__fadd_rn(q2, p.w),
                                          -__fmul_rn(2.0f, dot));
                    d2 = fmaxf(d2, 0.0f);
                    if (d2 <= R2) {
                        if (n < FRNQ_LIMIT || d2 < ld[FRNQ_LIMIT - 1]) {
                            int j = (n < FRNQ_LIMIT) ? n : (FRNQ_LIMIT - 1);
                            while (j > 0 && ld[j - 1] > d2) {
                                ld[j] = ld[j - 1];
                                li[j] = li[j - 1];
                                --j;
                            }
                            ld[j] = d2;
                            li[j] = t + k;
                            if (n < FRNQ_LIMIT) ++n;
                        }
                    }
                }
            }
        }
    }

    if (!active_q) return;

    // --- warp merge of 32 sorted lane lists: 32 rounds of argmin(d2, idx) ---
    int   pos = 0;
    float hd  = (n > 0) ? ld[0] : INF;
    int   hi  = (n > 0) ? li[0] : 0x7fffffff;
    float rd  = INF;
    int   ri  = -1;

    #pragma unroll
    for (int r = 0; r < FRNQ_LIMIT; ++r) {
        float bd = hd;
        int   bi = hi;
        int   bl = lane;
        #pragma unroll
        for (int off = 16; off > 0; off >>= 1) {
            float od = __shfl_xor_sync(0xffffffffu, bd, off);
            int   oi = __shfl_xor_sync(0xffffffffu, bi, off);
            int   ol = __shfl_xor_sync(0xffffffffu, bl, off);
            if (od < bd || (od == bd && oi < bi)) { bd = od; bi = oi; bl = ol; }
        }
        if (lane == bl) {
            ++pos;
            if (pos < n) { hd = ld[pos]; hi = li[pos]; }
            else         { hd = INF;     hi = 0x7fffffff; }
        }
        if (r == lane) { rd = bd; ri = bi; }
    }

    const size_t o   = (size_t)q * FRNQ_LIMIT + lane;
    const bool   val = (rd < 1e29f);
    out_idx[o]  = val ? (float)ri : -1.0f;
    out_dist[o] = val ? sqrtf(fmaxf(rd, 1e-12f)) : 0.0f;
}

extern "C" void kernel_launch(void* const* d_in, const int* in_sizes, int n_in,
                              void* d_out, int out_size)
{
    const float* points     = (const float*)d_in[0];
    const int*   row_splits = (const int*)  d_in[1];
    const float* qpts       = (const float*)d_in[2];
    const int*   q_splits   = (const int*)  d_in[3];

    const int n_rs = in_sizes[1];
    const int n_qs = in_sizes[3];
    const int Q    = in_sizes[2] / 3;

    float* out_idx  = (float*)d_out;
    float* out_dist = out_idx + (size_t)Q * FRNQ_LIMIT;

    const int blocks = (Q + FRNQ_WARPS_PER_BLOCK - 1) / FRNQ_WARPS_PER_BLOCK;
    frnq_kernel<<<blocks, FRNQ_THREADS>>>(points, row_splits, n_rs,
                                          qpts, q_splits, n_qs,
                                          Q, out_idx, out_dist);
}